// round 1
// baseline (speedup 1.0000x reference)
#include <cuda_runtime.h>

#define NROWS 131072
#define BB 32
#define OO 4096
#define FF 256
#define HH 8
#define HID 128
#define NBLK_A 2048  // NROWS / 64

// ---- scratch (static device globals: allocation-free kernel_launch) ----
__device__ float d_h[NROWS * HID];        // 64 MiB
__device__ float d_z[NROWS * HID];        // 64 MiB
__device__ float d_mask[NROWS];
__device__ float d_colpart[NBLK_A * 256]; // [block][sum(128), sumsq(128)]
__device__ float d_ss[256];               // scale[128], shift[128]
__device__ float d_t[NROWS * HH];         // logits+gumbel, later softmax weights
__device__ float d_partial[BB * 8 * HH * FF];

// ============================================================================
// kA: h = relu(x @ W_in + b_in); z = h @ W_blk + b_blk
//     + per-block BN column partial sums, + row mask (||x|| != 0)
// BM=64, BN=128(=HID), BK=16, 128 threads, 8x8 micro-tile per thread.
// ============================================================================
__global__ __launch_bounds__(128) void kA(
    const float* __restrict__ x, const float* __restrict__ Win,
    const float* __restrict__ bin, const float* __restrict__ Wblk,
    const float* __restrict__ bblk)
{
    __shared__ float hs[64 * 128];  // phase-1: first 1024 floats alias xs; epilogue: h tile
    __shared__ float ws[16 * 128];  // W tile; epilogue: aliases column-reduce buffer
    float* xs = hs;                 // 64 x 16 tile of x

    const int tid = threadIdx.x;
    const int tr = tid >> 4;   // 0..7  (rows tr*8 .. tr*8+7)
    const int tc = tid & 15;   // 0..15 (cols tc*8 .. tc*8+7)
    const int row0 = blockIdx.x * 64;

    float acc[8][8];
#pragma unroll
    for (int i = 0; i < 8; i++)
#pragma unroll
        for (int j = 0; j < 8; j++) acc[i][j] = 0.f;

    float sqv[2] = {0.f, 0.f};

    // ---------------- phase 1: x @ W_in ----------------
    for (int kk = 0; kk < FF; kk += 16) {
        __syncthreads();
#pragma unroll
        for (int t = 0; t < 2; t++) {
            int idx4 = tid + t * 128;           // 0..255 float4 slots (64 rows x 4)
            int r = idx4 >> 2, c4 = idx4 & 3;
            float4 v = *(const float4*)(x + (size_t)(row0 + r) * FF + kk + c4 * 4);
            *(float4*)(xs + r * 16 + c4 * 4) = v;
            sqv[t] += v.x * v.x + v.y * v.y + v.z * v.z + v.w * v.w;
        }
#pragma unroll
        for (int t = 0; t < 4; t++) {
            int idx4 = tid + t * 128;           // 16 rows x 32 float4
            int r = idx4 >> 5, c4 = idx4 & 31;
            *(float4*)(ws + r * 128 + c4 * 4) =
                *(const float4*)(Win + (size_t)(kk + r) * HID + c4 * 4);
        }
        __syncthreads();
#pragma unroll 4
        for (int k = 0; k < 16; k++) {
            float a[8];
#pragma unroll
            for (int i = 0; i < 8; i++) a[i] = xs[(tr * 8 + i) * 16 + k];
            float4 b0 = *(float4*)(ws + k * 128 + tc * 8);
            float4 b1 = *(float4*)(ws + k * 128 + tc * 8 + 4);
            float bv[8] = {b0.x, b0.y, b0.z, b0.w, b1.x, b1.y, b1.z, b1.w};
#pragma unroll
            for (int i = 0; i < 8; i++)
#pragma unroll
                for (int j = 0; j < 8; j++) acc[i][j] += a[i] * bv[j];
        }
    }
    __syncthreads();  // all reads of xs/ws done before hs is overwritten

    // row mask: per-t rows are fixed (row = tid/4 + t*32), 4 lanes share a row
#pragma unroll
    for (int t = 0; t < 2; t++) {
        float v = sqv[t];
        v += __shfl_down_sync(0xffffffffu, v, 2, 4);
        v += __shfl_down_sync(0xffffffffu, v, 1, 4);
        if ((tid & 3) == 0)
            d_mask[row0 + (tid >> 2) + t * 32] = (v > 0.f) ? 1.f : 0.f;
    }

    // bias + relu, write h to smem + global
    float binv[8];
#pragma unroll
    for (int j = 0; j < 8; j++) binv[j] = bin[tc * 8 + j];
#pragma unroll
    for (int i = 0; i < 8; i++) {
        int r = tr * 8 + i;
        float4 v0, v1;
        v0.x = fmaxf(acc[i][0] + binv[0], 0.f);
        v0.y = fmaxf(acc[i][1] + binv[1], 0.f);
        v0.z = fmaxf(acc[i][2] + binv[2], 0.f);
        v0.w = fmaxf(acc[i][3] + binv[3], 0.f);
        v1.x = fmaxf(acc[i][4] + binv[4], 0.f);
        v1.y = fmaxf(acc[i][5] + binv[5], 0.f);
        v1.z = fmaxf(acc[i][6] + binv[6], 0.f);
        v1.w = fmaxf(acc[i][7] + binv[7], 0.f);
        *(float4*)(hs + r * 128 + tc * 8)     = v0;
        *(float4*)(hs + r * 128 + tc * 8 + 4) = v1;
        *(float4*)(d_h + (size_t)(row0 + r) * HID + tc * 8)     = v0;
        *(float4*)(d_h + (size_t)(row0 + r) * HID + tc * 8 + 4) = v1;
    }
    __syncthreads();  // hs ready for phase 2

    // ---------------- phase 2: h @ W_blk ----------------
#pragma unroll
    for (int i = 0; i < 8; i++)
#pragma unroll
        for (int j = 0; j < 8; j++) acc[i][j] = 0.f;

    for (int kk = 0; kk < HID; kk += 16) {
        __syncthreads();
#pragma unroll
        for (int t = 0; t < 4; t++) {
            int idx4 = tid + t * 128;
            int r = idx4 >> 5, c4 = idx4 & 31;
            *(float4*)(ws + r * 128 + c4 * 4) =
                *(const float4*)(Wblk + (size_t)(kk + r) * HID + c4 * 4);
        }
        __syncthreads();
#pragma unroll 4
        for (int k = 0; k < 16; k++) {
            float a[8];
#pragma unroll
            for (int i = 0; i < 8; i++) a[i] = hs[(tr * 8 + i) * 128 + kk + k];
            float4 b0 = *(float4*)(ws + k * 128 + tc * 8);
            float4 b1 = *(float4*)(ws + k * 128 + tc * 8 + 4);
            float bv[8] = {b0.x, b0.y, b0.z, b0.w, b1.x, b1.y, b1.z, b1.w};
#pragma unroll
            for (int i = 0; i < 8; i++)
#pragma unroll
                for (int j = 0; j < 8; j++) acc[i][j] += a[i] * bv[j];
        }
    }
    __syncthreads();  // ws reads done; safe to reuse as reduce buffer

    // bias + store z + column partial sums / sumsq (deterministic)
    float bblkv[8];
#pragma unroll
    for (int j = 0; j < 8; j++) bblkv[j] = bblk[tc * 8 + j];
    float s_[8], q_[8];
#pragma unroll
    for (int j = 0; j < 8; j++) { s_[j] = 0.f; q_[j] = 0.f; }
#pragma unroll
    for (int i = 0; i < 8; i++) {
        int r = tr * 8 + i;
        float zv[8];
#pragma unroll
        for (int j = 0; j < 8; j++) {
            zv[j] = acc[i][j] + bblkv[j];
            s_[j] += zv[j];
            q_[j] += zv[j] * zv[j];
        }
        float4 v0 = make_float4(zv[0], zv[1], zv[2], zv[3]);
        float4 v1 = make_float4(zv[4], zv[5], zv[6], zv[7]);
        *(float4*)(d_z + (size_t)(row0 + r) * HID + tc * 8)     = v0;
        *(float4*)(d_z + (size_t)(row0 + r) * HID + tc * 8 + 4) = v1;
    }

    float* red = ws;  // 8 x 128 reduce buffer
#pragma unroll
    for (int j = 0; j < 8; j++) red[tr * 128 + tc * 8 + j] = s_[j];
    __syncthreads();
    if (tid < 128) {
        float t_ = 0.f;
#pragma unroll
        for (int r8 = 0; r8 < 8; r8++) t_ += red[r8 * 128 + tid];
        d_colpart[blockIdx.x * 256 + tid] = t_;
    }
    __syncthreads();
#pragma unroll
    for (int j = 0; j < 8; j++) red[tr * 128 + tc * 8 + j] = q_[j];
    __syncthreads();
    if (tid < 128) {
        float t_ = 0.f;
#pragma unroll
        for (int r8 = 0; r8 < 8; r8++) t_ += red[r8 * 128 + tid];
        d_colpart[blockIdx.x * 256 + 128 + tid] = t_;
    }
}

// ============================================================================
// kB: finalize BN stats -> scale/shift per column. grid=128 (one per col)
// ============================================================================
__global__ void kB(const float* __restrict__ gamma, const float* __restrict__ beta) {
    __shared__ float rs[256], rq[256];
    int c = blockIdx.x;
    int tid = threadIdx.x;
    float s = 0.f, q = 0.f;
    for (int i = tid; i < NBLK_A; i += 256) {
        s += d_colpart[i * 256 + c];
        q += d_colpart[i * 256 + 128 + c];
    }
    rs[tid] = s; rq[tid] = q;
    __syncthreads();
    for (int st = 128; st > 0; st >>= 1) {
        if (tid < st) { rs[tid] += rs[tid + st]; rq[tid] += rq[tid + st]; }
        __syncthreads();
    }
    if (tid == 0) {
        float mu  = rs[0] * (1.f / (float)NROWS);
        float var = rq[0] * (1.f / (float)NROWS) - mu * mu;
        float sc  = gamma[c] * rsqrtf(var + 1e-5f);
        d_ss[c]       = sc;
        d_ss[128 + c] = beta[c] - mu * sc;
    }
}

// ============================================================================
// kC: h2 = relu(z*scale+shift) + h; t = (h2 @ W_fc + b_fc)*mask + gumbel
// 32 rows per block, 256 threads. grid = 4096.
// ============================================================================
__global__ __launch_bounds__(256) void kC(
    const float* __restrict__ gumbel, const float* __restrict__ Wfc,
    const float* __restrict__ bfc)
{
    __shared__ float h2s[32 * 129];
    __shared__ float wfc_s[128 * 8];
    __shared__ float scs[128], shs[128], bfcs[8];

    int tid = threadIdx.x;
    int row0 = blockIdx.x * 32;

    if (tid < 128) { scs[tid] = d_ss[tid]; shs[tid] = d_ss[128 + tid]; }
    if (tid < 8)   bfcs[tid] = bfc[tid];
#pragma unroll
    for (int t = 0; t < 4; t++) wfc_s[tid + t * 256] = Wfc[tid + t * 256];
    __syncthreads();

#pragma unroll
    for (int t = 0; t < 16; t++) {
        int e = tid + t * 256;        // 0..4095
        int r = e >> 7, c = e & 127;
        size_t g = (size_t)(row0 + r) * HID + c;
        float zn = d_z[g] * scs[c] + shs[c];
        h2s[r * 129 + c] = fmaxf(zn, 0.f) + d_h[g];
    }
    __syncthreads();

    int r = tid >> 3, j = tid & 7;
    float accv = bfcs[j];
#pragma unroll
    for (int k = 0; k < 128; k++)
        accv += h2s[r * 129 + k] * wfc_s[k * 8 + j];

    int grow = row0 + r;
    d_t[(size_t)grow * 8 + j] = accv * d_mask[grow] + gumbel[(size_t)grow * 8 + j];
}

// ============================================================================
// kD: softmax over O (=4096) for each (b,h), in-place in d_t. grid = 256.
// ============================================================================
__global__ __launch_bounds__(256) void kD() {
    __shared__ float red[256];
    int b = blockIdx.x >> 3, h = blockIdx.x & 7;
    size_t base = (size_t)b * OO * HH + h;
    int tid = threadIdx.x;

    float m = -1e30f;
    for (int o = tid; o < OO; o += 256) m = fmaxf(m, d_t[base + (size_t)o * 8]);
    red[tid] = m; __syncthreads();
    for (int s = 128; s > 0; s >>= 1) {
        if (tid < s) red[tid] = fmaxf(red[tid], red[tid + s]);
        __syncthreads();
    }
    m = red[0];
    __syncthreads();

    float sum = 0.f;
    for (int o = tid; o < OO; o += 256) sum += expf(d_t[base + (size_t)o * 8] - m);
    red[tid] = sum; __syncthreads();
    for (int s = 128; s > 0; s >>= 1) {
        if (tid < s) red[tid] += red[tid + s];
        __syncthreads();
    }
    float inv = 1.f / red[0];

    for (int o = tid; o < OO; o += 256) {
        size_t idx = base + (size_t)o * 8;
        d_t[idx] = expf(d_t[idx] - m) * inv;
    }
}

// ============================================================================
// kE: partial pooled[b][oc][h][f] = sum_{o in chunk} w[b,o,h]*x[b,o,f]
// grid = 32*8 = 256 blocks (b, o-chunk of 512), 256 threads (=F).
// ============================================================================
__global__ __launch_bounds__(256) void kE(const float* __restrict__ x) {
    __shared__ float wsm[64 * 8];
    int b = blockIdx.x >> 3, oc = blockIdx.x & 7;
    int tid = threadIdx.x;
    float acc[8];
#pragma unroll
    for (int h = 0; h < 8; h++) acc[h] = 0.f;
    int o0 = oc * 512;

    for (int chunk = 0; chunk < 512; chunk += 64) {
        size_t wbase = ((size_t)b * OO + o0 + chunk) * 8;
        *(float2*)(wsm + tid * 2) = *(const float2*)(d_t + wbase + tid * 2);
        __syncthreads();
#pragma unroll 4
        for (int oo = 0; oo < 64; oo++) {
            float xv = x[((size_t)b * OO + o0 + chunk + oo) * FF + tid];
#pragma unroll
            for (int h = 0; h < 8; h++) acc[h] += wsm[oo * 8 + h] * xv;
        }
        __syncthreads();
    }
#pragma unroll
    for (int h = 0; h < 8; h++)
        d_partial[(((size_t)b * 8 + oc) * 8 + h) * FF + tid] = acc[h];
}

// ============================================================================
// kF: out[b][h][f] = sum_oc partial. grid = 256 (b*8+h), 256 threads (f).
// ============================================================================
__global__ __launch_bounds__(256) void kF(float* __restrict__ out) {
    int bh = blockIdx.x;            // b*8 + h
    int b = bh >> 3, h = bh & 7;
    int f = threadIdx.x;
    float s = 0.f;
#pragma unroll
    for (int oc = 0; oc < 8; oc++)
        s += d_partial[(((size_t)b * 8 + oc) * 8 + h) * FF + f];
    out[(size_t)bh * FF + f] = s;
}

// ============================================================================
extern "C" void kernel_launch(void* const* d_in, const int* in_sizes, int n_in,
                              void* d_out, int out_size) {
    const float* x      = (const float*)d_in[0];
    const float* gumbel = (const float*)d_in[1];
    const float* Win    = (const float*)d_in[2];
    const float* bin    = (const float*)d_in[3];
    const float* Wblk   = (const float*)d_in[4];
    const float* bblk   = (const float*)d_in[5];
    const float* gamma  = (const float*)d_in[6];
    const float* beta   = (const float*)d_in[7];
    const float* Wfc    = (const float*)d_in[8];
    const float* bfc    = (const float*)d_in[9];
    float* out = (float*)d_out;

    kA<<<NBLK_A, 128>>>(x, Win, bin, Wblk, bblk);
    kB<<<128, 256>>>(gamma, beta);
    kC<<<NROWS / 32, 256>>>(gumbel, Wfc, bfc);
    kD<<<BB * HH, 256>>>();
    kE<<<BB * 8, 256>>>(x);
    kF<<<BB * HH, 256>>>(out);
}

// round 3
// speedup vs baseline: 1.6286x; 1.6286x over previous
#include <cuda_runtime.h>
#include <cuda_bf16.h>
#include <cstdint>

#define NROWS 131072
#define BB 32
#define OO 4096
#define FF 256
#define HH 8
#define HID 128
#define NBLK_A 1024   // NROWS / 128

// ---------------- scratch (device globals) ----------------
__device__ float d_h[NROWS * HID];
__device__ float d_z[NROWS * HID];
__device__ float d_mask[NROWS];
__device__ float d_colpart[NBLK_A * 256];
__device__ float d_ss[256];
__device__ float d_t[NROWS * HH];
__device__ float d_partial[BB * 8 * HH * FF];
// pre-split weights, transposed to [N][K], bf16 hi/lo
__device__ __nv_bfloat16 d_WinT_hi[HID * FF];
__device__ __nv_bfloat16 d_WinT_lo[HID * FF];
__device__ __nv_bfloat16 d_WblkT_hi[HID * HID];
__device__ __nv_bfloat16 d_WblkT_lo[HID * HID];

// ---------------- smem layout for kA (bytes) ----------------
// tiles: 128 rows x 128 cols bf16, row stride 136 elem (272 B)
#define TILE_BYTES 34816           // 128 * 272
#define AS_HI 0
#define AS_LO 34816
#define BS_HI 69632
#define BS_LO 104448
#define ROWSQ 139264               // 128 floats
#define WSUM  139776               // 8*128 floats
#define WSQ   143872               // 8*128 floats
#define SMEM_TOTAL 147968

// ---------------- helpers ----------------
__device__ __forceinline__ uint32_t smem_u32(const void* p) {
    uint32_t a;
    asm("{ .reg .u64 t; cvta.to.shared.u64 t, %1; cvt.u32.u64 %0, t; }" : "=r"(a) : "l"(p));
    return a;
}
__device__ __forceinline__ void ldsm4(uint32_t* r, uint32_t addr) {
    asm volatile("ldmatrix.sync.aligned.m8n8.x4.shared.b16 {%0,%1,%2,%3}, [%4];"
        : "=r"(r[0]), "=r"(r[1]), "=r"(r[2]), "=r"(r[3]) : "r"(addr));
}
__device__ __forceinline__ void ldsm2(uint32_t& r0, uint32_t& r1, uint32_t addr) {
    asm volatile("ldmatrix.sync.aligned.m8n8.x2.shared.b16 {%0,%1}, [%2];"
        : "=r"(r0), "=r"(r1) : "r"(addr));
}
__device__ __forceinline__ void mma16816(float* c, const uint32_t* a, uint32_t b0, uint32_t b1) {
    asm volatile("mma.sync.aligned.m16n8k16.row.col.f32.bf16.bf16.f32 "
        "{%0,%1,%2,%3}, {%4,%5,%6,%7}, {%8,%9}, {%0,%1,%2,%3};"
        : "+f"(c[0]), "+f"(c[1]), "+f"(c[2]), "+f"(c[3])
        : "r"(a[0]), "r"(a[1]), "r"(a[2]), "r"(a[3]), "r"(b0), "r"(b1));
}
__device__ __forceinline__ uint32_t pack2(float a, float b, uint32_t& lo) {
    __nv_bfloat16 ha = __float2bfloat16(a), hb = __float2bfloat16(b);
    __nv_bfloat16 la = __float2bfloat16(a - __bfloat162float(ha));
    __nv_bfloat16 lb = __float2bfloat16(b - __bfloat162float(hb));
    __nv_bfloat162 hp = __halves2bfloat162(ha, hb);
    __nv_bfloat162 lp = __halves2bfloat162(la, lb);
    lo = *reinterpret_cast<uint32_t*>(&lp);
    return *reinterpret_cast<uint32_t*>(&hp);
}

// ============================================================================
// kW: pre-split weights into bf16 hi/lo, transposed to [N][K]
// ============================================================================
__global__ void kW(const float* __restrict__ Win, const float* __restrict__ Wblk) {
    int e = blockIdx.x * 256 + threadIdx.x;
    if (e < HID * FF) {
        int n = e >> 8, k = e & 255;
        float v = Win[(size_t)k * HID + n];
        __nv_bfloat16 hi = __float2bfloat16(v);
        d_WinT_hi[e] = hi;
        d_WinT_lo[e] = __float2bfloat16(v - __bfloat162float(hi));
    }
    if (e < HID * HID) {
        int n = e >> 7, k = e & 127;
        float v = Wblk[(size_t)k * HID + n];
        __nv_bfloat16 hi = __float2bfloat16(v);
        d_WblkT_hi[e] = hi;
        d_WblkT_lo[e] = __float2bfloat16(v - __bfloat162float(hi));
    }
}

// ============================================================================
// kA_mma: h = relu(x@Win+b); z = h@Wblk+b; BN col partials; row mask
// 128 rows/CTA, 8 warps, each warp = 16 rows x 128 cols in registers.
// bf16 hi/lo split (3 MMA terms) via mma.sync m16n8k16.
// ============================================================================
__global__ __launch_bounds__(256, 1) void kA_mma(
    const float* __restrict__ x, const float* __restrict__ bin,
    const float* __restrict__ bblk)
{
    extern __shared__ char smem[];
    const uint32_t sb = smem_u32(smem);
    const int tid = threadIdx.x;
    const int lane = tid & 31;
    const int w = tid >> 5;
    const int row0 = blockIdx.x * 128;

    float* rowsq = (float*)(smem + ROWSQ);
    float* wS = (float*)(smem + WSUM);
    float* wQ = (float*)(smem + WSQ);
    if (tid < 128) rowsq[tid] = 0.f;
    __syncthreads();

    float acc[16][4];
#pragma unroll
    for (int nt = 0; nt < 16; nt++)
#pragma unroll
        for (int j = 0; j < 4; j++) acc[nt][j] = 0.f;

    // per-lane ldmatrix base addresses
    const uint32_t aHi = sb + AS_HI + (uint32_t)(((w * 16 + (lane & 15)) * 136 + ((lane >> 4) << 3)) * 2);
    const uint32_t aLo = aHi + TILE_BYTES;
    const uint32_t bHi = sb + BS_HI + (uint32_t)(((lane & 7) * 136 + ((lane >> 3) & 1) * 8) * 2);
    const uint32_t bLo = bHi + TILE_BYTES;

    // ---------------- GEMM1: K=256 in 2 chunks of 128 ----------------
    for (int ck = 0; ck < 2; ck++) {
        if (ck) __syncthreads();  // prior chunk's smem reads complete

        // A: x[row0..+128, ck*128..+128) -> bf16 hi/lo, + row sumsq
#pragma unroll
        for (int i = 0; i < 16; i++) {
            int idx = tid + i * 256;
            int r = idx >> 5, c4 = idx & 31;   // r = w + i*8
            float4 v = *(const float4*)(x + (size_t)(row0 + r) * FF + ck * 128 + c4 * 4);
            float sq = v.x * v.x + v.y * v.y + v.z * v.z + v.w * v.w;
#pragma unroll
            for (int off = 16; off; off >>= 1)
                sq += __shfl_xor_sync(0xffffffffu, sq, off);
            if (lane == 0) rowsq[r] += sq;
            uint32_t l0, l1;
            uint32_t h0 = pack2(v.x, v.y, l0);
            uint32_t h1 = pack2(v.z, v.w, l1);
            uint32_t off4 = (uint32_t)(r * 272 + c4 * 8);
            *(uint2*)(smem + AS_HI + off4) = make_uint2(h0, h1);
            *(uint2*)(smem + AS_LO + off4) = make_uint2(l0, l1);
        }
        // B: WinT chunk [128n][128k] hi/lo
#pragma unroll
        for (int i = 0; i < 8; i++) {
            int idx = tid + i * 256;
            int n = idx >> 4, q = idx & 15;
            uint32_t doff = (uint32_t)(n * 272 + q * 16);
            *(uint4*)(smem + BS_HI + doff) = *(const uint4*)(d_WinT_hi + (size_t)n * FF + ck * 128 + q * 8);
            *(uint4*)(smem + BS_LO + doff) = *(const uint4*)(d_WinT_lo + (size_t)n * FF + ck * 128 + q * 8);
        }
        if (ck == 1 && lane == 0) {
#pragma unroll
            for (int i = 0; i < 16; i++) {
                int r = w + i * 8;
                d_mask[row0 + r] = (rowsq[r] > 0.f) ? 1.f : 0.f;
            }
        }
        __syncthreads();

#pragma unroll
        for (int ks = 0; ks < 8; ks++) {
            uint32_t ah[4], al[4];
            ldsm4(ah, aHi + ks * 32);
            ldsm4(al, aLo + ks * 32);
#pragma unroll
            for (int nt = 0; nt < 16; nt++) {
                uint32_t bh0, bh1, bl0, bl1;
                ldsm2(bh0, bh1, bHi + nt * 2176 + ks * 32);
                ldsm2(bl0, bl1, bLo + nt * 2176 + ks * 32);
                mma16816(acc[nt], ah, bh0, bh1);
                mma16816(acc[nt], ah, bl0, bl1);
                mma16816(acc[nt], al, bh0, bh1);
            }
        }
    }

    // ---------------- epilogue 1: h = relu(acc + bin) ----------------
    const int qrow = lane >> 2, qcol = lane & 3;
    const int r0 = w * 16 + qrow;
#pragma unroll
    for (int nt = 0; nt < 16; nt++) {
        int c0 = nt * 8 + qcol * 2;
        float b0v = bin[c0], b1v = bin[c0 + 1];
        float h00 = fmaxf(acc[nt][0] + b0v, 0.f);
        float h01 = fmaxf(acc[nt][1] + b1v, 0.f);
        float h10 = fmaxf(acc[nt][2] + b0v, 0.f);
        float h11 = fmaxf(acc[nt][3] + b1v, 0.f);
        *(float2*)(d_h + (size_t)(row0 + r0) * HID + c0)     = make_float2(h00, h01);
        *(float2*)(d_h + (size_t)(row0 + r0 + 8) * HID + c0) = make_float2(h10, h11);
        uint32_t lo0, lo1;
        uint32_t hi0 = pack2(h00, h01, lo0);
        uint32_t hi1 = pack2(h10, h11, lo1);
        *(uint32_t*)(smem + AS_HI + (r0 * 136 + c0) * 2)       = hi0;
        *(uint32_t*)(smem + AS_LO + (r0 * 136 + c0) * 2)       = lo0;
        *(uint32_t*)(smem + AS_HI + ((r0 + 8) * 136 + c0) * 2) = hi1;
        *(uint32_t*)(smem + AS_LO + ((r0 + 8) * 136 + c0) * 2) = lo1;
        acc[nt][0] = acc[nt][1] = acc[nt][2] = acc[nt][3] = 0.f;
    }
    __syncthreads();  // GEMM1 Bs reads + As(h) writes complete

    // B: WblkT [128n][128k] hi/lo
#pragma unroll
    for (int i = 0; i < 8; i++) {
        int idx = tid + i * 256;
        int n = idx >> 4, q = idx & 15;
        uint32_t doff = (uint32_t)(n * 272 + q * 16);
        *(uint4*)(smem + BS_HI + doff) = *(const uint4*)(d_WblkT_hi + (size_t)n * HID + q * 8);
        *(uint4*)(smem + BS_LO + doff) = *(const uint4*)(d_WblkT_lo + (size_t)n * HID + q * 8);
    }
    __syncthreads();

    // ---------------- GEMM2: z = h @ Wblk, K=128 ----------------
#pragma unroll
    for (int ks = 0; ks < 8; ks++) {
        uint32_t ah[4], al[4];
        ldsm4(ah, aHi + ks * 32);
        ldsm4(al, aLo + ks * 32);
#pragma unroll
        for (int nt = 0; nt < 16; nt++) {
            uint32_t bh0, bh1, bl0, bl1;
            ldsm2(bh0, bh1, bHi + nt * 2176 + ks * 32);
            ldsm2(bl0, bl1, bLo + nt * 2176 + ks * 32);
            mma16816(acc[nt], ah, bh0, bh1);
            mma16816(acc[nt], ah, bl0, bl1);
            mma16816(acc[nt], al, bh0, bh1);
        }
    }

    // ---------------- epilogue 2: z + bias, BN partial sums ----------------
#pragma unroll
    for (int nt = 0; nt < 16; nt++) {
        int c0 = nt * 8 + qcol * 2;
        float b0v = bblk[c0], b1v = bblk[c0 + 1];
        float z00 = acc[nt][0] + b0v, z01 = acc[nt][1] + b1v;
        float z10 = acc[nt][2] + b0v, z11 = acc[nt][3] + b1v;
        *(float2*)(d_z + (size_t)(row0 + r0) * HID + c0)     = make_float2(z00, z01);
        *(float2*)(d_z + (size_t)(row0 + r0 + 8) * HID + c0) = make_float2(z10, z11);
        float s0 = z00 + z10, s1 = z01 + z11;
        float q0 = z00 * z00 + z10 * z10, q1 = z01 * z01 + z11 * z11;
#pragma unroll
        for (int off = 4; off <= 16; off <<= 1) {
            s0 += __shfl_xor_sync(0xffffffffu, s0, off);
            s1 += __shfl_xor_sync(0xffffffffu, s1, off);
            q0 += __shfl_xor_sync(0xffffffffu, q0, off);
            q1 += __shfl_xor_sync(0xffffffffu, q1, off);
        }
        if (lane < 4) {
            wS[w * 128 + c0] = s0; wS[w * 128 + c0 + 1] = s1;
            wQ[w * 128 + c0] = q0; wQ[w * 128 + c0 + 1] = q1;
        }
    }
    __syncthreads();
    if (tid < 128) {
        float s = 0.f, q = 0.f;
#pragma unroll
        for (int ww = 0; ww < 8; ww++) { s += wS[ww * 128 + tid]; q += wQ[ww * 128 + tid]; }
        d_colpart[blockIdx.x * 256 + tid] = s;
        d_colpart[blockIdx.x * 256 + 128 + tid] = q;
    }
}

// ============================================================================
// kB: finalize BN stats -> scale/shift
// ============================================================================
__global__ void kB(const float* __restrict__ gamma, const float* __restrict__ beta) {
    __shared__ float rs[256], rq[256];
    int c = blockIdx.x;
    int tid = threadIdx.x;
    float s = 0.f, q = 0.f;
    for (int i = tid; i < NBLK_A; i += 256) {
        s += d_colpart[i * 256 + c];
        q += d_colpart[i * 256 + 128 + c];
    }
    rs[tid] = s; rq[tid] = q;
    __syncthreads();
    for (int st = 128; st > 0; st >>= 1) {
        if (tid < st) { rs[tid] += rs[tid + st]; rq[tid] += rq[tid + st]; }
        __syncthreads();
    }
    if (tid == 0) {
        float mu  = rs[0] * (1.f / (float)NROWS);
        float var = rq[0] * (1.f / (float)NROWS) - mu * mu;
        float sc  = gamma[c] * rsqrtf(var + 1e-5f);
        d_ss[c]       = sc;
        d_ss[128 + c] = beta[c] - mu * sc;
    }
}

// ============================================================================
// kC: h2 = relu(bn(z)) + h; t = (h2@Wfc + b)*mask + gumbel
// ============================================================================
__global__ __launch_bounds__(256) void kC(
    const float* __restrict__ gumbel, const float* __restrict__ Wfc,
    const float* __restrict__ bfc)
{
    __shared__ float h2s[32 * 129];
    __shared__ float wfc_s[128 * 8];
    __shared__ float scs[128], shs[128], bfcs[8];

    int tid = threadIdx.x;
    int row0 = blockIdx.x * 32;

    if (tid < 128) { scs[tid] = d_ss[tid]; shs[tid] = d_ss[128 + tid]; }
    if (tid < 8)   bfcs[tid] = bfc[tid];
#pragma unroll
    for (int t = 0; t < 4; t++) wfc_s[tid + t * 256] = Wfc[tid + t * 256];
    __syncthreads();

#pragma unroll
    for (int t = 0; t < 16; t++) {
        int e = tid + t * 256;
        int r = e >> 7, c = e & 127;
        size_t g = (size_t)(row0 + r) * HID + c;
        float zn = d_z[g] * scs[c] + shs[c];
        h2s[r * 129 + c] = fmaxf(zn, 0.f) + d_h[g];
    }
    __syncthreads();

    int r = tid >> 3, j = tid & 7;
    float accv = bfcs[j];
#pragma unroll
    for (int k = 0; k < 128; k++)
        accv += h2s[r * 129 + k] * wfc_s[k * 8 + j];

    int grow = row0 + r;
    d_t[(size_t)grow * 8 + j] = accv * d_mask[grow] + gumbel[(size_t)grow * 8 + j];
}

// ============================================================================
// kD: softmax over O per (b,h) — one block per b, coalesced float4 loads
// ============================================================================
__global__ __launch_bounds__(256) void kD() {
    __shared__ float wred[8][8];  // [warp][h]
    int b = blockIdx.x;
    int tid = threadIdx.x, lane = tid & 31, w = tid >> 5;
    size_t base = (size_t)b * OO * HH;

    float m[8];
#pragma unroll
    for (int h = 0; h < 8; h++) m[h] = -1e30f;
    for (int o = tid; o < OO; o += 256) {
        const float4* p = (const float4*)(d_t + base + (size_t)o * 8);
        float4 v0 = p[0], v1 = p[1];
        m[0] = fmaxf(m[0], v0.x); m[1] = fmaxf(m[1], v0.y);
        m[2] = fmaxf(m[2], v0.z); m[3] = fmaxf(m[3], v0.w);
        m[4] = fmaxf(m[4], v1.x); m[5] = fmaxf(m[5], v1.y);
        m[6] = fmaxf(m[6], v1.z); m[7] = fmaxf(m[7], v1.w);
    }
#pragma unroll
    for (int h = 0; h < 8; h++)
#pragma unroll
        for (int off = 16; off; off >>= 1)
            m[h] = fmaxf(m[h], __shfl_xor_sync(0xffffffffu, m[h], off));
    if (lane == 0) {
#pragma unroll
        for (int h = 0; h < 8; h++) wred[w][h] = m[h];
    }
    __syncthreads();
    float M[8];
#pragma unroll
    for (int h = 0; h < 8; h++) {
        float t = wred[0][h];
#pragma unroll
        for (int ww = 1; ww < 8; ww++) t = fmaxf(t, wred[ww][h]);
        M[h] = t;
    }
    __syncthreads();

    float s[8];
#pragma unroll
    for (int h = 0; h < 8; h++) s[h] = 0.f;
    for (int o = tid; o < OO; o += 256) {
        float4* p = (float4*)(d_t + base + (size_t)o * 8);
        float4 v0 = p[0], v1 = p[1];
        v0.x = expf(v0.x - M[0]); v0.y = expf(v0.y - M[1]);
        v0.z = expf(v0.z - M[2]); v0.w = expf(v0.w - M[3]);
        v1.x = expf(v1.x - M[4]); v1.y = expf(v1.y - M[5]);
        v1.z = expf(v1.z - M[6]); v1.w = expf(v1.w - M[7]);
        s[0] += v0.x; s[1] += v0.y; s[2] += v0.z; s[3] += v0.w;
        s[4] += v1.x; s[5] += v1.y; s[6] += v1.z; s[7] += v1.w;
        p[0] = v0; p[1] = v1;
    }
#pragma unroll
    for (int h = 0; h < 8; h++)
#pragma unroll
        for (int off = 16; off; off >>= 1)
            s[h] += __shfl_xor_sync(0xffffffffu, s[h], off);
    if (lane == 0) {
#pragma unroll
        for (int h = 0; h < 8; h++) wred[w][h] = s[h];
    }
    __syncthreads();
    float inv[8];
#pragma unroll
    for (int h = 0; h < 8; h++) {
        float t = 0.f;
#pragma unroll
        for (int ww = 0; ww < 8; ww++) t += wred[ww][h];
        inv[h] = 1.f / t;
    }

    for (int o = tid; o < OO; o += 256) {
        float4* p = (float4*)(d_t + base + (size_t)o * 8);
        float4 v0 = p[0], v1 = p[1];
        v0.x *= inv[0]; v0.y *= inv[1]; v0.z *= inv[2]; v0.w *= inv[3];
        v1.x *= inv[4]; v1.y *= inv[5]; v1.z *= inv[6]; v1.w *= inv[7];
        p[0] = v0; p[1] = v1;
    }
}

// ============================================================================
// kE: pooled partials  partial[b][oc][h][f] = sum_o w[b,o,h] x[b,o,f]
// ============================================================================
__global__ __launch_bounds__(256) void kE(const float* __restrict__ x) {
    __shared__ float wsm[64 * 8];
    int b = blockIdx.x >> 3, oc = blockIdx.x & 7;
    int tid = threadIdx.x;
    float acc[8];
#pragma unroll
    for (int h = 0; h < 8; h++) acc[h] = 0.f;
    int o0 = oc * 512;

    for (int chunk = 0; chunk < 512; chunk += 64) {
        size_t wbase = ((size_t)b * OO + o0 + chunk) * 8;
        *(float2*)(wsm + tid * 2) = *(const float2*)(d_t + wbase + tid * 2);
        __syncthreads();
#pragma unroll 4
        for (int oo = 0; oo < 64; oo++) {
            float xv = x[((size_t)b * OO + o0 + chunk + oo) * FF + tid];
#pragma unroll
            for (int h = 0; h < 8; h++) acc[h] += wsm[oo * 8 + h] * xv;
        }
        __syncthreads();
    }
#pragma unroll
    for (int h = 0; h < 8; h++)
        d_partial[(((size_t)b * 8 + oc) * 8 + h) * FF + tid] = acc[h];
}

// ============================================================================
// kF: final reduce
// ============================================================================
__global__ __launch_bounds__(256) void kF(float* __restrict__ out) {
    int bh = blockIdx.x;
    int b = bh >> 3, h = bh & 7;
    int f = threadIdx.x;
    float s = 0.f;
#pragma unroll
    for (int oc = 0; oc < 8; oc++)
        s += d_partial[(((size_t)b * 8 + oc) * 8 + h) * FF + f];
    out[(size_t)bh * FF + f] = s;
}

// ============================================================================
extern "C" void kernel_launch(void* const* d_in, const int* in_sizes, int n_in,
                              void* d_out, int out_size) {
    const float* x      = (const float*)d_in[0];
    const float* gumbel = (const float*)d_in[1];
    const float* Win    = (const float*)d_in[2];
    const float* bin    = (const float*)d_in[3];
    const float* Wblk   = (const float*)d_in[4];
    const float* bblk   = (const float*)d_in[5];
    const float* gamma  = (const float*)d_in[6];
    const float* beta   = (const float*)d_in[7];
    const float* Wfc    = (const float*)d_in[8];
    const float* bfc    = (const float*)d_in[9];
    float* out = (float*)d_out;

    static bool attr_set = false;
    if (!attr_set) {
        cudaFuncSetAttribute(kA_mma, cudaFuncAttributeMaxDynamicSharedMemorySize, SMEM_TOTAL);
        attr_set = true;
    }

    kW<<<128, 256>>>(Win, Wblk);
    kA_mma<<<NBLK_A, 256, SMEM_TOTAL>>>(x, bin, bblk);
    kB<<<128, 256>>>(gamma, beta);
    kC<<<NROWS / 32, 256>>>(gumbel, Wfc, bfc);
    kD<<<BB, 256>>>();
    kE<<<BB * 8, 256>>>(x);
    kF<<<BB * HH, 256>>>(out);
}

// round 5
// speedup vs baseline: 2.1005x; 1.2898x over previous
#include <cuda_runtime.h>
#include <cuda_bf16.h>
#include <cstdint>

#define NROWS 131072
#define BB 32
#define OO 4096
#define FF 256
#define HH 8
#define HID 128
#define NBLK_A 1024   // NROWS / 128

// ---------------- scratch (device globals) ----------------
__device__ float d_h[NROWS * HID];
__device__ float d_z[NROWS * HID];
__device__ float d_mask[NROWS];
__device__ float d_colpart[NBLK_A * 256];
__device__ float d_ss[256];
__device__ float d_t[NROWS * HH];
__device__ float d_partial[BB * 32 * HH * FF];
// pre-split weights, transposed to [N][K], bf16 hi/lo
__device__ __nv_bfloat16 d_WinT_hi[HID * FF];
__device__ __nv_bfloat16 d_WinT_lo[HID * FF];
__device__ __nv_bfloat16 d_WblkT_hi[HID * HID];
__device__ __nv_bfloat16 d_WblkT_lo[HID * HID];

// ---------------- smem layout for kA (bytes) ----------------
// tiles: 128 rows x 128 cols bf16, row stride 136 elem (272 B)
#define TILE_BYTES 34816           // 128 * 272
#define AS_HI 0
#define AS_LO 34816
#define BS_HI 69632
#define BS_LO 104448
#define ROWSQ 139264               // 128 floats
#define WSUM  139776               // 8*128 floats
#define WSQ   143872               // 8*128 floats
#define SMEM_TOTAL 147968

// ---------------- smem layout for kC (bytes) ----------------
#define KC_WFH 69632               // 8 x 136 bf16
#define KC_WFL 71808
#define KC_SC  73984
#define KC_SH  74496
#define KC_BFC 75008
#define KC_SMEM 75040

// ---------------- helpers ----------------
__device__ __forceinline__ uint32_t smem_u32(const void* p) {
    uint32_t a;
    asm("{ .reg .u64 t; cvta.to.shared.u64 t, %1; cvt.u32.u64 %0, t; }" : "=r"(a) : "l"(p));
    return a;
}
__device__ __forceinline__ void ldsm4(uint32_t* r, uint32_t addr) {
    asm volatile("ldmatrix.sync.aligned.m8n8.x4.shared.b16 {%0,%1,%2,%3}, [%4];"
        : "=r"(r[0]), "=r"(r[1]), "=r"(r[2]), "=r"(r[3]) : "r"(addr));
}
__device__ __forceinline__ void ldsm2(uint32_t& r0, uint32_t& r1, uint32_t addr) {
    asm volatile("ldmatrix.sync.aligned.m8n8.x2.shared.b16 {%0,%1}, [%2];"
        : "=r"(r0), "=r"(r1) : "r"(addr));
}
__device__ __forceinline__ void mma16816(float* c, const uint32_t* a, uint32_t b0, uint32_t b1) {
    asm volatile("mma.sync.aligned.m16n8k16.row.col.f32.bf16.bf16.f32 "
        "{%0,%1,%2,%3}, {%4,%5,%6,%7}, {%8,%9}, {%0,%1,%2,%3};"
        : "+f"(c[0]), "+f"(c[1]), "+f"(c[2]), "+f"(c[3])
        : "r"(a[0]), "r"(a[1]), "r"(a[2]), "r"(a[3]), "r"(b0), "r"(b1));
}
__device__ __forceinline__ uint32_t pack2(float a, float b, uint32_t& lo) {
    __nv_bfloat16 ha = __float2bfloat16(a), hb = __float2bfloat16(b);
    __nv_bfloat16 la = __float2bfloat16(a - __bfloat162float(ha));
    __nv_bfloat16 lb = __float2bfloat16(b - __bfloat162float(hb));
    __nv_bfloat162 hp = __halves2bfloat162(ha, hb);
    __nv_bfloat162 lp = __halves2bfloat162(la, lb);
    lo = *reinterpret_cast<uint32_t*>(&lp);
    return *reinterpret_cast<uint32_t*>(&hp);
}

// ============================================================================
// kW: pre-split weights into bf16 hi/lo, transposed to [N][K]
// ============================================================================
__global__ void kW(const float* __restrict__ Win, const float* __restrict__ Wblk) {
    int e = blockIdx.x * 256 + threadIdx.x;
    if (e < HID * FF) {
        int n = e >> 8, k = e & 255;
        float v = Win[(size_t)k * HID + n];
        __nv_bfloat16 hi = __float2bfloat16(v);
        d_WinT_hi[e] = hi;
        d_WinT_lo[e] = __float2bfloat16(v - __bfloat162float(hi));
    }
    if (e < HID * HID) {
        int n = e >> 7, k = e & 127;
        float v = Wblk[(size_t)k * HID + n];
        __nv_bfloat16 hi = __float2bfloat16(v);
        d_WblkT_hi[e] = hi;
        d_WblkT_lo[e] = __float2bfloat16(v - __bfloat162float(hi));
    }
}

// ============================================================================
// kA_mma: h = relu(x@Win+b); z = h@Wblk+b; BN col partials; row mask
// 128 rows/CTA, 16 warps: warp = 16 rows x 64 cols. bf16 hi/lo 3-term MMA.
// ============================================================================
__global__ __launch_bounds__(512, 1) void kA_mma(
    const float* __restrict__ x, const float* __restrict__ bin,
    const float* __restrict__ bblk)
{
    extern __shared__ char smem[];
    const uint32_t sb = smem_u32(smem);
    const int tid = threadIdx.x;
    const int lane = tid & 31;
    const int w = tid >> 5;
    const int wr = w >> 1;        // row group 0..7 (16 rows each)
    const int wc = w & 1;         // col half 0..1 (64 cols each)
    const int row0 = blockIdx.x * 128;

    float* rowsq = (float*)(smem + ROWSQ);
    float* wS = (float*)(smem + WSUM);
    float* wQ = (float*)(smem + WSQ);
    if (tid < 128) rowsq[tid] = 0.f;
    __syncthreads();

    float acc[8][4];
#pragma unroll
    for (int nt = 0; nt < 8; nt++)
#pragma unroll
        for (int j = 0; j < 4; j++) acc[nt][j] = 0.f;

    // ldmatrix lane bases
    const uint32_t aHi = sb + AS_HI +
        (uint32_t)((wr * 16 + (lane & 15)) * 272 + ((lane >> 4) << 3) * 2);
    const uint32_t aLo = aHi + TILE_BYTES;
    const uint32_t bBase = sb + BS_HI + (uint32_t)(wc * 64 * 272 +
        ((lane & 7) + ((lane >> 4) << 3)) * 272 + ((lane >> 3) & 1) * 16);

    // ---------------- GEMM1: K=256 in 2 chunks of 128 ----------------
    for (int ck = 0; ck < 2; ck++) {
        if (ck) __syncthreads();

        // A: x chunk -> bf16 hi/lo + row-nonzero vote
#pragma unroll
        for (int i = 0; i < 8; i++) {
            int idx = tid + i * 512;
            int r = idx >> 5, c4 = idx & 31;
            float4 v = *(const float4*)(x + (size_t)(row0 + r) * FF + ck * 128 + c4 * 4);
            int nz = (v.x != 0.f) | (v.y != 0.f) | (v.z != 0.f) | (v.w != 0.f);
            if (__any_sync(0xffffffffu, nz) && lane == 0) rowsq[r] = 1.f;
            uint32_t l0, l1;
            uint32_t h0 = pack2(v.x, v.y, l0);
            uint32_t h1 = pack2(v.z, v.w, l1);
            uint32_t off4 = (uint32_t)(r * 272 + c4 * 8);
            *(uint2*)(smem + AS_HI + off4) = make_uint2(h0, h1);
            *(uint2*)(smem + AS_LO + off4) = make_uint2(l0, l1);
        }
        // B: WinT chunk [128n][128k] hi/lo
#pragma unroll
        for (int i = 0; i < 4; i++) {
            int idx = tid + i * 512;
            int n = idx >> 4, q = idx & 15;
            uint32_t doff = (uint32_t)(n * 272 + q * 16);
            *(uint4*)(smem + BS_HI + doff) = *(const uint4*)(d_WinT_hi + (size_t)n * FF + ck * 128 + q * 8);
            *(uint4*)(smem + BS_LO + doff) = *(const uint4*)(d_WinT_lo + (size_t)n * FF + ck * 128 + q * 8);
        }
        __syncthreads();

#pragma unroll
        for (int ks = 0; ks < 8; ks++) {
            uint32_t ah[4], al[4];
            ldsm4(ah, aHi + ks * 32);
            ldsm4(al, aLo + ks * 32);
#pragma unroll
            for (int p = 0; p < 4; p++) {
                uint32_t bh[4], bl[4];
                ldsm4(bh, bBase + p * 4352 + ks * 32);
                ldsm4(bl, bBase + p * 4352 + ks * 32 + TILE_BYTES);
                mma16816(acc[2 * p],     ah, bh[0], bh[1]);
                mma16816(acc[2 * p],     ah, bl[0], bl[1]);
                mma16816(acc[2 * p],     al, bh[0], bh[1]);
                mma16816(acc[2 * p + 1], ah, bh[2], bh[3]);
                mma16816(acc[2 * p + 1], ah, bl[2], bl[3]);
                mma16816(acc[2 * p + 1], al, bh[2], bh[3]);
            }
        }
    }

    // RACE FIX: warps (wr,0) and (wr,1) read ALL k-columns of the same 16 A
    // rows in the mainloop above; epilogue 1 overwrites those smem rows with
    // h. Must drain all GEMM1 ldmatrix reads block-wide before overwriting.
    __syncthreads();

    // ---------------- epilogue 1: h = relu(acc + bin) ----------------
    const int qrow = lane >> 2, qcol = lane & 3;
    const int r0 = wr * 16 + qrow;
#pragma unroll
    for (int nt = 0; nt < 8; nt++) {
        int c0 = wc * 64 + nt * 8 + qcol * 2;
        float b0v = bin[c0], b1v = bin[c0 + 1];
        float h00 = fmaxf(acc[nt][0] + b0v, 0.f);
        float h01 = fmaxf(acc[nt][1] + b1v, 0.f);
        float h10 = fmaxf(acc[nt][2] + b0v, 0.f);
        float h11 = fmaxf(acc[nt][3] + b1v, 0.f);
        *(float2*)(d_h + (size_t)(row0 + r0) * HID + c0)     = make_float2(h00, h01);
        *(float2*)(d_h + (size_t)(row0 + r0 + 8) * HID + c0) = make_float2(h10, h11);
        uint32_t lo0, lo1;
        uint32_t hi0 = pack2(h00, h01, lo0);
        uint32_t hi1 = pack2(h10, h11, lo1);
        *(uint32_t*)(smem + AS_HI + (r0 * 136 + c0) * 2)       = hi0;
        *(uint32_t*)(smem + AS_LO + (r0 * 136 + c0) * 2)       = lo0;
        *(uint32_t*)(smem + AS_HI + ((r0 + 8) * 136 + c0) * 2) = hi1;
        *(uint32_t*)(smem + AS_LO + ((r0 + 8) * 136 + c0) * 2) = lo1;
        acc[nt][0] = acc[nt][1] = acc[nt][2] = acc[nt][3] = 0.f;
    }
    __syncthreads();

    // B: WblkT [128n][128k] hi/lo
#pragma unroll
    for (int i = 0; i < 4; i++) {
        int idx = tid + i * 512;
        int n = idx >> 4, q = idx & 15;
        uint32_t doff = (uint32_t)(n * 272 + q * 16);
        *(uint4*)(smem + BS_HI + doff) = *(const uint4*)(d_WblkT_hi + (size_t)n * HID + q * 8);
        *(uint4*)(smem + BS_LO + doff) = *(const uint4*)(d_WblkT_lo + (size_t)n * HID + q * 8);
    }
    __syncthreads();

    // ---------------- GEMM2: z = h @ Wblk, K=128 ----------------
#pragma unroll
    for (int ks = 0; ks < 8; ks++) {
        uint32_t ah[4], al[4];
        ldsm4(ah, aHi + ks * 32);
        ldsm4(al, aLo + ks * 32);
#pragma unroll
        for (int p = 0; p < 4; p++) {
            uint32_t bh[4], bl[4];
            ldsm4(bh, bBase + p * 4352 + ks * 32);
            ldsm4(bl, bBase + p * 4352 + ks * 32 + TILE_BYTES);
            mma16816(acc[2 * p],     ah, bh[0], bh[1]);
            mma16816(acc[2 * p],     ah, bl[0], bl[1]);
            mma16816(acc[2 * p],     al, bh[0], bh[1]);
            mma16816(acc[2 * p + 1], ah, bh[2], bh[3]);
            mma16816(acc[2 * p + 1], ah, bl[2], bl[3]);
            mma16816(acc[2 * p + 1], al, bh[2], bh[3]);
        }
    }

    // ---------------- epilogue 2: z + bias, BN partial sums ----------------
#pragma unroll
    for (int nt = 0; nt < 8; nt++) {
        int c0 = wc * 64 + nt * 8 + qcol * 2;
        float b0v = bblk[c0], b1v = bblk[c0 + 1];
        float z00 = acc[nt][0] + b0v, z01 = acc[nt][1] + b1v;
        float z10 = acc[nt][2] + b0v, z11 = acc[nt][3] + b1v;
        *(float2*)(d_z + (size_t)(row0 + r0) * HID + c0)     = make_float2(z00, z01);
        *(float2*)(d_z + (size_t)(row0 + r0 + 8) * HID + c0) = make_float2(z10, z11);
        float s0 = z00 + z10, s1 = z01 + z11;
        float q0 = z00 * z00 + z10 * z10, q1 = z01 * z01 + z11 * z11;
#pragma unroll
        for (int off = 4; off <= 16; off <<= 1) {
            s0 += __shfl_xor_sync(0xffffffffu, s0, off);
            s1 += __shfl_xor_sync(0xffffffffu, s1, off);
            q0 += __shfl_xor_sync(0xffffffffu, q0, off);
            q1 += __shfl_xor_sync(0xffffffffu, q1, off);
        }
        if (lane < 4) {
            wS[wr * 128 + c0] = s0; wS[wr * 128 + c0 + 1] = s1;
            wQ[wr * 128 + c0] = q0; wQ[wr * 128 + c0 + 1] = q1;
        }
    }
    __syncthreads();
    if (tid < 128) {
        float s = 0.f, q = 0.f;
#pragma unroll
        for (int g = 0; g < 8; g++) { s += wS[g * 128 + tid]; q += wQ[g * 128 + tid]; }
        d_colpart[blockIdx.x * 256 + tid] = s;
        d_colpart[blockIdx.x * 256 + 128 + tid] = q;
        d_mask[row0 + tid] = rowsq[tid];
    }
}

// ============================================================================
// kB: finalize BN stats -> scale/shift
// ============================================================================
__global__ void kB(const float* __restrict__ gamma, const float* __restrict__ beta) {
    __shared__ float rs[256], rq[256];
    int c = blockIdx.x;
    int tid = threadIdx.x;
    float s = 0.f, q = 0.f;
    for (int i = tid; i < NBLK_A; i += 256) {
        s += d_colpart[i * 256 + c];
        q += d_colpart[i * 256 + 128 + c];
    }
    rs[tid] = s; rq[tid] = q;
    __syncthreads();
    for (int st = 128; st > 0; st >>= 1) {
        if (tid < st) { rs[tid] += rs[tid + st]; rq[tid] += rq[tid + st]; }
        __syncthreads();
    }
    if (tid == 0) {
        float mu  = rs[0] * (1.f / (float)NROWS);
        float var = rq[0] * (1.f / (float)NROWS) - mu * mu;
        float sc  = gamma[c] * rsqrtf(var + 1e-5f);
        d_ss[c]       = sc;
        d_ss[128 + c] = beta[c] - mu * sc;
    }
}

// ============================================================================
// kC_mma: h2 = relu(bn(z)) + h; t = (h2@Wfc + b)*mask + gumbel — via MMA
// 128 rows/CTA, 8 warps: warp = 16 rows x 8 heads.
// ============================================================================
__global__ __launch_bounds__(256, 2) void kC_mma(
    const float* __restrict__ gumbel, const float* __restrict__ Wfc,
    const float* __restrict__ bfc)
{
    extern __shared__ char smem[];
    const uint32_t sb = smem_u32(smem);
    const int tid = threadIdx.x;
    const int lane = tid & 31;
    const int w = tid >> 5;
    const int row0 = blockIdx.x * 128;

    float* scs  = (float*)(smem + KC_SC);
    float* shs  = (float*)(smem + KC_SH);
    float* bfcs = (float*)(smem + KC_BFC);

    // stage WfcT hi/lo: [8n][136k]
#pragma unroll
    for (int u = 0; u < 4; u++) {
        int e = tid + u * 256;         // 0..1023, Wfc[k][j] row-major
        int k = e >> 3, j = e & 7;
        float v = Wfc[e];
        __nv_bfloat16 hi = __float2bfloat16(v);
        __nv_bfloat16 lo = __float2bfloat16(v - __bfloat162float(hi));
        *(__nv_bfloat16*)(smem + KC_WFH + (j * 136 + k) * 2) = hi;
        *(__nv_bfloat16*)(smem + KC_WFL + (j * 136 + k) * 2) = lo;
    }
    if (tid < 128) { scs[tid] = d_ss[tid]; shs[tid] = d_ss[128 + tid]; }
    if (tid < 8)   bfcs[tid] = bfc[tid];
    __syncthreads();

    // convert: h2 tiles per warp (16 x 128), bf16 hi/lo
    char* ah = smem + w * 8704;
    char* al = ah + 4352;
    {
        const int c = lane * 4;
        float4 sc4 = *(float4*)(scs + c);
        float4 sh4 = *(float4*)(shs + c);
#pragma unroll
        for (int i = 0; i < 16; i++) {
            size_t g = (size_t)(row0 + w * 16 + i) * HID + c;
            float4 zv = *(const float4*)(d_z + g);
            float4 hv = *(const float4*)(d_h + g);
            float t0 = fmaxf(zv.x * sc4.x + sh4.x, 0.f) + hv.x;
            float t1 = fmaxf(zv.y * sc4.y + sh4.y, 0.f) + hv.y;
            float t2 = fmaxf(zv.z * sc4.z + sh4.z, 0.f) + hv.z;
            float t3 = fmaxf(zv.w * sc4.w + sh4.w, 0.f) + hv.w;
            uint32_t l0, l1;
            uint32_t h0 = pack2(t0, t1, l0);
            uint32_t h1 = pack2(t2, t3, l1);
            *(uint2*)(ah + (i * 136 + c) * 2) = make_uint2(h0, h1);
            *(uint2*)(al + (i * 136 + c) * 2) = make_uint2(l0, l1);
        }
    }
    __syncwarp();

    float acc[4] = {0.f, 0.f, 0.f, 0.f};
    const uint32_t aH = sb + w * 8704 +
        (uint32_t)(((lane & 15) * 136 + ((lane >> 4) << 3)) * 2);
    const uint32_t aL = aH + 4352;
    const uint32_t bH = sb + KC_WFH +
        (uint32_t)(((lane & 7) * 136 + ((lane >> 3) & 1) * 8) * 2);
    const uint32_t bL = bH + 2176;
#pragma unroll
    for (int ks = 0; ks < 8; ks++) {
        uint32_t ahf[4], alf[4];
        ldsm4(ahf, aH + ks * 32);
        ldsm4(alf, aL + ks * 32);
        uint32_t bh0, bh1, bl0, bl1;
        ldsm2(bh0, bh1, bH + ks * 32);
        ldsm2(bl0, bl1, bL + ks * 32);
        mma16816(acc, ahf, bh0, bh1);
        mma16816(acc, ahf, bl0, bl1);
        mma16816(acc, alf, bh0, bh1);
    }

    const int qrow = lane >> 2, qcol = lane & 3;
    const int r0 = row0 + w * 16 + qrow;
    float m0 = d_mask[r0], m1 = d_mask[r0 + 8];
    float b0 = bfcs[qcol * 2], b1 = bfcs[qcol * 2 + 1];
    float2 g0 = *(const float2*)(gumbel + (size_t)r0 * 8 + qcol * 2);
    float2 g1 = *(const float2*)(gumbel + (size_t)(r0 + 8) * 8 + qcol * 2);
    *(float2*)(d_t + (size_t)r0 * 8 + qcol * 2) =
        make_float2((acc[0] + b0) * m0 + g0.x, (acc[1] + b1) * m0 + g0.y);
    *(float2*)(d_t + (size_t)(r0 + 8) * 8 + qcol * 2) =
        make_float2((acc[2] + b0) * m1 + g1.x, (acc[3] + b1) * m1 + g1.y);
}

// ============================================================================
// kD: softmax over O per (b,h) — one block per b, coalesced float4 loads
// ============================================================================
__global__ __launch_bounds__(256) void kD() {
    __shared__ float wred[8][8];
    int b = blockIdx.x;
    int tid = threadIdx.x, lane = tid & 31, w = tid >> 5;
    size_t base = (size_t)b * OO * HH;

    float m[8];
#pragma unroll
    for (int h = 0; h < 8; h++) m[h] = -1e30f;
    for (int o = tid; o < OO; o += 256) {
        const float4* p = (const float4*)(d_t + base + (size_t)o * 8);
        float4 v0 = p[0], v1 = p[1];
        m[0] = fmaxf(m[0], v0.x); m[1] = fmaxf(m[1], v0.y);
        m[2] = fmaxf(m[2], v0.z); m[3] = fmaxf(m[3], v0.w);
        m[4] = fmaxf(m[4], v1.x); m[5] = fmaxf(m[5], v1.y);
        m[6] = fmaxf(m[6], v1.z); m[7] = fmaxf(m[7], v1.w);
    }
#pragma unroll
    for (int h = 0; h < 8; h++)
#pragma unroll
        for (int off = 16; off; off >>= 1)
            m[h] = fmaxf(m[h], __shfl_xor_sync(0xffffffffu, m[h], off));
    if (lane == 0) {
#pragma unroll
        for (int h = 0; h < 8; h++) wred[w][h] = m[h];
    }
    __syncthreads();
    float M[8];
#pragma unroll
    for (int h = 0; h < 8; h++) {
        float t = wred[0][h];
#pragma unroll
        for (int ww = 1; ww < 8; ww++) t = fmaxf(t, wred[ww][h]);
        M[h] = t;
    }
    __syncthreads();

    float s[8];
#pragma unroll
    for (int h = 0; h < 8; h++) s[h] = 0.f;
    for (int o = tid; o < OO; o += 256) {
        float4* p = (float4*)(d_t + base + (size_t)o * 8);
        float4 v0 = p[0], v1 = p[1];
        v0.x = expf(v0.x - M[0]); v0.y = expf(v0.y - M[1]);
        v0.z = expf(v0.z - M[2]); v0.w = expf(v0.w - M[3]);
        v1.x = expf(v1.x - M[4]); v1.y = expf(v1.y - M[5]);
        v1.z = expf(v1.z - M[6]); v1.w = expf(v1.w - M[7]);
        s[0] += v0.x; s[1] += v0.y; s[2] += v0.z; s[3] += v0.w;
        s[4] += v1.x; s[5] += v1.y; s[6] += v1.z; s[7] += v1.w;
        p[0] = v0; p[1] = v1;
    }
#pragma unroll
    for (int h = 0; h < 8; h++)
#pragma unroll
        for (int off = 16; off; off >>= 1)
            s[h] += __shfl_xor_sync(0xffffffffu, s[h], off);
    if (lane == 0) {
#pragma unroll
        for (int h = 0; h < 8; h++) wred[w][h] = s[h];
    }
    __syncthreads();
    float inv[8];
#pragma unroll
    for (int h = 0; h < 8; h++) {
        float t = 0.f;
#pragma unroll
        for (int ww = 0; ww < 8; ww++) t += wred[ww][h];
        inv[h] = 1.f / t;
    }

    for (int o = tid; o < OO; o += 256) {
        float4* p = (float4*)(d_t + base + (size_t)o * 8);
        float4 v0 = p[0], v1 = p[1];
        v0.x *= inv[0]; v0.y *= inv[1]; v0.z *= inv[2]; v0.w *= inv[3];
        v1.x *= inv[4]; v1.y *= inv[5]; v1.z *= inv[6]; v1.w *= inv[7];
        p[0] = v0; p[1] = v1;
    }
}

// ============================================================================
// kE: pooled partials, float4 x loads; 4-way o-split per block
// ============================================================================
__global__ __launch_bounds__(256) void kE(const float* __restrict__ x) {
    __shared__ float wsm[64 * 8];
    int b = blockIdx.x >> 3, oc = blockIdx.x & 7;
    int tid = threadIdx.x;
    int fq = tid & 63;        // float4 index over F
    int og = tid >> 6;        // 0..3 o-subgroup
    float acc[8][4];
#pragma unroll
    for (int h = 0; h < 8; h++)
#pragma unroll
        for (int j = 0; j < 4; j++) acc[h][j] = 0.f;
    int o0 = oc * 512;

    for (int chunk = 0; chunk < 512; chunk += 64) {
        size_t wbase = ((size_t)b * OO + o0 + chunk) * 8;
        *(float2*)(wsm + tid * 2) = *(const float2*)(d_t + wbase + tid * 2);
        __syncthreads();
#pragma unroll 4
        for (int t = 0; t < 16; t++) {
            int oo = og * 16 + t;
            float4 xv = *(const float4*)(x + ((size_t)b * OO + o0 + chunk + oo) * FF + fq * 4);
#pragma unroll
            for (int h = 0; h < 8; h++) {
                float wv = wsm[oo * 8 + h];
                acc[h][0] += wv * xv.x; acc[h][1] += wv * xv.y;
                acc[h][2] += wv * xv.z; acc[h][3] += wv * xv.w;
            }
        }
        __syncthreads();
    }
#pragma unroll
    for (int h = 0; h < 8; h++)
        *(float4*)(d_partial + (((size_t)b * 32 + oc * 4 + og) * 8 + h) * FF + fq * 4) =
            make_float4(acc[h][0], acc[h][1], acc[h][2], acc[h][3]);
}

// ============================================================================
// kF: final reduce over 32 partials
// ============================================================================
__global__ __launch_bounds__(256) void kF(float* __restrict__ out) {
    int bh = blockIdx.x;
    int b = bh >> 3, h = bh & 7;
    int f = threadIdx.x;
    float s = 0.f;
#pragma unroll
    for (int p = 0; p < 32; p++)
        s += d_partial[(((size_t)b * 32 + p) * 8 + h) * FF + f];
    out[(size_t)bh * FF + f] = s;
}

// ============================================================================
extern "C" void kernel_launch(void* const* d_in, const int* in_sizes, int n_in,
                              void* d_out, int out_size) {
    const float* x      = (const float*)d_in[0];
    const float* gumbel = (const float*)d_in[1];
    const float* Win    = (const float*)d_in[2];
    const float* bin    = (const float*)d_in[3];
    const float* Wblk   = (const float*)d_in[4];
    const float* bblk   = (const float*)d_in[5];
    const float* gamma  = (const float*)d_in[6];
    const float* beta   = (const float*)d_in[7];
    const float* Wfc    = (const float*)d_in[8];
    const float* bfc    = (const float*)d_in[9];
    float* out = (float*)d_out;

    cudaFuncSetAttribute(kA_mma, cudaFuncAttributeMaxDynamicSharedMemorySize, SMEM_TOTAL);
    cudaFuncSetAttribute(kC_mma, cudaFuncAttributeMaxDynamicSharedMemorySize, KC_SMEM);

    kW<<<128, 256>>>(Win, Wblk);
    kA_mma<<<NBLK_A, 512, SMEM_TOTAL>>>(x, bin, bblk);
    kB<<<128, 256>>>(gamma, beta);
    kC_mma<<<NBLK_A, 256, KC_SMEM>>>(gumbel, Wfc, bfc);
    kD<<<BB, 256>>>();
    kE<<<BB * 8, 256>>>(x);
    kF<<<BB * HH, 256>>>(out);
}